// round 3
// baseline (speedup 1.0000x reference)
#include <cuda_runtime.h>
#include <mma.h>
#include <math_constants.h>

using namespace nvcuda;

// Problem constants
#define BATCH    16384
#define NODE_DIM 172
#define TIME_DIM 100
#define EDGE_DIM 172
#define OUT_DIM  272          // NODE_DIM + TIME_DIM, = 4*68
#define KEY_DIM  444          // NODE_DIM + EDGE_DIM + TIME_DIM
#define KEY_PAD  448          // padded to multiple of 16/64
#define NNB      20
#define NH       4
#define DH       68
#define DH_PAD   80           // padded to multiple of 16
#define SCALE    0.12126781251816648f  // 68^-0.5
#define LN_EPS   1e-5f

// Scratch (static device globals -- no allocation)
__device__ float g_q  [BATCH * OUT_DIM];                 // [B,272]
__device__ float g_qk [BATCH * NH * KEY_PAD];            // [B,4,448] (pad cols = 0)
__device__ float g_z  [BATCH * NH * KEY_PAD];            // [B,4,448] (pad cols = 0)
__device__ float g_ctx[BATCH * NH * DH_PAD];             // [B,4,80]  (pad cols = 0)

// ---------------------------------------------------------------------------
// K1: q[b,o] = sum_c q_in[b,c] * Wq[o,c];  q_in = [node | time]
// GEMM M=B, N=272 (grid.y tiles of 64, guarded), K=272. tf32 wmma m16n16k8.
// ---------------------------------------------------------------------------
__global__ __launch_bounds__(256) void k1_qproj(
    const float* __restrict__ node, const float* __restrict__ timef,
    const float* __restrict__ Wq)
{
    const int bm = blockIdx.x * 64;
    const int bn = blockIdx.y * 64;
    __shared__ float As[64][16];
    __shared__ float Bs[16][72];   // [k][o], padded

    wmma::fragment<wmma::accumulator, 16, 16, 8, float> c0, c1;
    wmma::fill_fragment(c0, 0.0f);
    wmma::fill_fragment(c1, 0.0f);

    const int tid  = threadIdx.x;
    const int warp = tid >> 5;
    const int rb   = warp >> 1;           // row block (0..3)
    const int cb   = (warp & 1) * 2;      // first col block of the pair

    for (int kc = 0; kc < OUT_DIM; kc += 16) {
        for (int i = tid; i < 64 * 16; i += 256) {
            int r = i >> 4, cc = i & 15;
            int gc = kc + cc;
            As[r][cc] = (gc < NODE_DIM) ? node[(bm + r) * NODE_DIM + gc]
                                        : timef[(bm + r) * TIME_DIM + gc - NODE_DIM];
        }
        for (int i = tid; i < 64 * 16; i += 256) {
            int o = i >> 4, k = i & 15;
            int go = bn + o;
            Bs[k][o] = (go < OUT_DIM) ? Wq[go * OUT_DIM + kc + k] : 0.0f;
        }
        __syncthreads();
#pragma unroll
        for (int ks = 0; ks < 2; ks++) {
            wmma::fragment<wmma::matrix_a, 16, 16, 8, wmma::precision::tf32, wmma::row_major> a;
            wmma::fragment<wmma::matrix_b, 16, 16, 8, wmma::precision::tf32, wmma::row_major> b0, b1;
            wmma::load_matrix_sync(a, &As[rb * 16][ks * 8], 16);
#pragma unroll
            for (int i = 0; i < a.num_elements; i++) a.x[i] = wmma::__float_to_tf32(a.x[i]);
            wmma::load_matrix_sync(b0, &Bs[ks * 8][cb * 16], 72);
            wmma::load_matrix_sync(b1, &Bs[ks * 8][(cb + 1) * 16], 72);
#pragma unroll
            for (int i = 0; i < b0.num_elements; i++) {
                b0.x[i] = wmma::__float_to_tf32(b0.x[i]);
                b1.x[i] = wmma::__float_to_tf32(b1.x[i]);
            }
            wmma::mma_sync(c0, a, b0, c0);
            wmma::mma_sync(c1, a, b1, c1);
        }
        __syncthreads();
    }
    int oc0 = bn + cb * 16;
    int oc1 = oc0 + 16;
    if (oc0 < OUT_DIM)
        wmma::store_matrix_sync(&g_q[(bm + rb * 16) * OUT_DIM + oc0], c0, OUT_DIM, wmma::mem_row_major);
    if (oc1 < OUT_DIM)
        wmma::store_matrix_sync(&g_q[(bm + rb * 16) * OUT_DIM + oc1], c1, OUT_DIM, wmma::mem_row_major);
}

// ---------------------------------------------------------------------------
// K2: qk[b,h,j] = sum_d q[b,h*68+d] * Wk[h*68+d, j]
// Per-head GEMM: M=B, N=444 (7 tiles of 64; cols >=444 compute 0), K=68.
// Writes padded [B,4,448]; pad columns become exact zeros.
// ---------------------------------------------------------------------------
__global__ __launch_bounds__(256) void k2_qk(const float* __restrict__ Wk)
{
    const int bm = blockIdx.x * 64;
    const int bn = blockIdx.y * 64;
    const int h  = blockIdx.z;
    __shared__ float As[64][16];
    __shared__ float Bs[16][72];

    wmma::fragment<wmma::accumulator, 16, 16, 8, float> c0, c1;
    wmma::fill_fragment(c0, 0.0f);
    wmma::fill_fragment(c1, 0.0f);

    const int tid  = threadIdx.x;
    const int warp = tid >> 5;
    const int rb   = warp >> 1;
    const int cb   = (warp & 1) * 2;

    for (int kc = 0; kc < DH + 15; kc += 16) {   // kc = 0,16,32,48,64
        for (int i = tid; i < 64 * 16; i += 256) {
            int r = i >> 4, cc = i & 15;
            int gk = kc + cc;
            As[r][cc] = (gk < DH) ? g_q[(bm + r) * OUT_DIM + h * DH + gk] : 0.0f;
        }
        for (int i = tid; i < 64 * 16; i += 256) {
            int k = i >> 6, j = i & 63;          // coalesced along j
            int gk = kc + k, gj = bn + j;
            Bs[k][j] = (gk < DH && gj < KEY_DIM) ? Wk[(h * DH + gk) * KEY_DIM + gj] : 0.0f;
        }
        __syncthreads();
#pragma unroll
        for (int ks = 0; ks < 2; ks++) {
            wmma::fragment<wmma::matrix_a, 16, 16, 8, wmma::precision::tf32, wmma::row_major> a;
            wmma::fragment<wmma::matrix_b, 16, 16, 8, wmma::precision::tf32, wmma::row_major> b0, b1;
            wmma::load_matrix_sync(a, &As[rb * 16][ks * 8], 16);
#pragma unroll
            for (int i = 0; i < a.num_elements; i++) a.x[i] = wmma::__float_to_tf32(a.x[i]);
            wmma::load_matrix_sync(b0, &Bs[ks * 8][cb * 16], 72);
            wmma::load_matrix_sync(b1, &Bs[ks * 8][(cb + 1) * 16], 72);
#pragma unroll
            for (int i = 0; i < b0.num_elements; i++) {
                b0.x[i] = wmma::__float_to_tf32(b0.x[i]);
                b1.x[i] = wmma::__float_to_tf32(b1.x[i]);
            }
            wmma::mma_sync(c0, a, b0, c0);
            wmma::mma_sync(c1, a, b1, c1);
        }
        __syncthreads();
    }
    // rows stride across b = NH*KEY_PAD; always store (pad cols are exact 0)
    wmma::store_matrix_sync(&g_qk[((bm + rb * 16) * NH + h) * KEY_PAD + bn + cb * 16],
                            c0, NH * KEY_PAD, wmma::mem_row_major);
    wmma::store_matrix_sync(&g_qk[((bm + rb * 16) * NH + h) * KEY_PAD + bn + (cb + 1) * 16],
                            c1, NH * KEY_PAD, wmma::mem_row_major);
}

// ---------------------------------------------------------------------------
// K3: streaming attention. One CTA per batch element.
// scores -> masked stable softmax -> z[b,h,:] = sum_n p[h,n]*kv_in[b,n,:]
// ---------------------------------------------------------------------------
__global__ __launch_bounds__(256) void k3_attn(
    const float* __restrict__ nbr_node, const float* __restrict__ nbr_time,
    const float* __restrict__ nbr_edge, const int* __restrict__ masks)
{
    const int b = blockIdx.x;
    __shared__ float kv[NNB][KEY_PAD];    // 35.0 KB
    __shared__ float qks[NH][KEY_PAD];    // 7.0 KB
    __shared__ float sc[NH][32];

    const int tid = threadIdx.x;

    const float* np = nbr_node + (size_t)b * NNB * NODE_DIM;
    for (int i = tid; i < NNB * NODE_DIM; i += 256)
        kv[i / NODE_DIM][i % NODE_DIM] = np[i];
    const float* ep = nbr_edge + (size_t)b * NNB * EDGE_DIM;
    for (int i = tid; i < NNB * EDGE_DIM; i += 256)
        kv[i / EDGE_DIM][NODE_DIM + i % EDGE_DIM] = ep[i];
    const float* tp = nbr_time + (size_t)b * NNB * TIME_DIM;
    for (int i = tid; i < NNB * TIME_DIM; i += 256)
        kv[i / TIME_DIM][NODE_DIM + EDGE_DIM + i % TIME_DIM] = tp[i];
    for (int i = tid; i < NNB * (KEY_PAD - KEY_DIM); i += 256)
        kv[i >> 2][KEY_DIM + (i & 3)] = 0.0f;
    const float* qp = g_qk + (size_t)b * NH * KEY_PAD;
    float* qflat = &qks[0][0];
    for (int i = tid; i < NH * KEY_PAD; i += 256) qflat[i] = qp[i];
    __syncthreads();

    const int warp = tid >> 5, lane = tid & 31;

    // 80 score dot-products (len 448, pads are zero); 10 per warp
    for (int p = warp * 10; p < warp * 10 + 10; p++) {
        int h = p / NNB, n = p % NNB;
        float acc = 0.0f;
        for (int j = lane; j < KEY_PAD; j += 32)
            acc += qks[h][j] * kv[n][j];
#pragma unroll
        for (int off = 16; off; off >>= 1) acc += __shfl_xor_sync(0xffffffffu, acc, off);
        if (lane == 0) {
            float s = acc * SCALE;
            sc[h][n] = (masks[b * NNB + n] == 0) ? -1e10f : s;
        }
    }
    __syncthreads();

    // softmax per head (warps 0..3)
    if (warp < NH) {
        float s = (lane < NNB) ? sc[warp][lane] : -CUDART_INF_F;
        float m = s;
#pragma unroll
        for (int off = 16; off; off >>= 1) m = fmaxf(m, __shfl_xor_sync(0xffffffffu, m, off));
        float e = (lane < NNB) ? expf(s - m) : 0.0f;
        float sum = e;
#pragma unroll
        for (int off = 16; off; off >>= 1) sum += __shfl_xor_sync(0xffffffffu, sum, off);
        if (lane < NNB) sc[warp][lane] = e / sum;
    }
    __syncthreads();

    // z aggregation (pads stay exact zero since kv pad = 0)
    float* zp = g_z + (size_t)b * NH * KEY_PAD;
    for (int i = tid; i < NH * KEY_PAD; i += 256) {
        int h = i / KEY_PAD, j = i % KEY_PAD;
        float acc = 0.0f;
#pragma unroll
        for (int n = 0; n < NNB; n++) acc += sc[h][n] * kv[n][j];
        zp[i] = acc;
    }
}

// ---------------------------------------------------------------------------
// K4: ctx[b,h*68+d] = sum_j z[b,h,j] * Wv[h*68+d, j]
// Per-head GEMM: M=B (tile 128), N=80 (5 col tiles; d>=68 compute 0), K=448.
// Output padded [B,4,80].
// ---------------------------------------------------------------------------
__global__ __launch_bounds__(256) void k4_ctx(const float* __restrict__ Wv)
{
    const int bm = blockIdx.x * 128;
    const int h  = blockIdx.z;
    __shared__ float As[128][16];
    __shared__ float Bs[16][88];     // [k(j)][d], padded

    wmma::fragment<wmma::accumulator, 16, 16, 8, float> c[5];
#pragma unroll
    for (int i = 0; i < 5; i++) wmma::fill_fragment(c[i], 0.0f);

    const int tid  = threadIdx.x;
    const int warp = tid >> 5;       // row block

    for (int kc = 0; kc < KEY_PAD; kc += 16) {
        for (int i = tid; i < 128 * 16; i += 256) {
            int r = i >> 4, cc = i & 15;
            As[r][cc] = g_z[((bm + r) * NH + h) * KEY_PAD + kc + cc];
        }
        for (int i = tid; i < 80 * 16; i += 256) {
            int d = i >> 4, k = i & 15;     // coalesced along k (= j, contiguous in Wv)
            int gj = kc + k;
            Bs[k][d] = (d < DH && gj < KEY_DIM) ? Wv[(h * DH + d) * KEY_DIM + gj] : 0.0f;
        }
        __syncthreads();
#pragma unroll
        for (int ks = 0; ks < 2; ks++) {
            wmma::fragment<wmma::matrix_a, 16, 16, 8, wmma::precision::tf32, wmma::row_major> a;
            wmma::load_matrix_sync(a, &As[warp * 16][ks * 8], 16);
#pragma unroll
            for (int i = 0; i < a.num_elements; i++) a.x[i] = wmma::__float_to_tf32(a.x[i]);
#pragma unroll
            for (int cb = 0; cb < 5; cb++) {
                wmma::fragment<wmma::matrix_b, 16, 16, 8, wmma::precision::tf32, wmma::row_major> bfr;
                wmma::load_matrix_sync(bfr, &Bs[ks * 8][cb * 16], 88);
#pragma unroll
                for (int i = 0; i < bfr.num_elements; i++) bfr.x[i] = wmma::__float_to_tf32(bfr.x[i]);
                wmma::mma_sync(c[cb], a, bfr, c[cb]);
            }
        }
        __syncthreads();
    }
#pragma unroll
    for (int cb = 0; cb < 5; cb++)
        wmma::store_matrix_sync(&g_ctx[((bm + warp * 16) * NH + h) * DH_PAD + cb * 16],
                                c[cb], NH * DH_PAD, wmma::mem_row_major);
}

// ---------------------------------------------------------------------------
// K5: out = LN(ctx @ Wr^T + br + q_in) * gamma + beta
// CTA handles 32 rows x full 272 cols (needed for the row-wise LayerNorm).
// ---------------------------------------------------------------------------
__global__ __launch_bounds__(256) void k5_out(
    const float* __restrict__ node, const float* __restrict__ timef,
    const float* __restrict__ Wr, const float* __restrict__ br,
    const float* __restrict__ gamma, const float* __restrict__ beta,
    float* __restrict__ out)
{
    const int bm = blockIdx.x * 32;
    __shared__ float raw[32 * 280];           // 35 KB, aliased:
    float* As   = raw;                        //  [32][16]  (512 floats)
    float* Bs   = raw + 512;                  //  [16][280] (4480 floats)
    float* outs = raw;                        //  [32][280] (after GEMM)

    const int tid  = threadIdx.x;
    const int warp = tid >> 5;
    const int lane = tid & 31;

    // warp w owns tiles t = w + 8k (t<34): rb = t/17, cb = t%17
    wmma::fragment<wmma::accumulator, 16, 16, 8, float> c[5];
    const int ntile = (warp < 2) ? 5 : 4;
#pragma unroll
    for (int i = 0; i < 5; i++) wmma::fill_fragment(c[i], 0.0f);

    for (int kc = 0; kc < OUT_DIM; kc += 16) {
        for (int i = tid; i < 32 * 16; i += 256) {
            int r = i >> 4, cc = i & 15;
            int o = kc + cc;
            int hh = o / DH, d = o % DH;      // gather from padded ctx
            As[r * 16 + cc] = g_ctx[((bm + r) * NH + hh) * DH_PAD + d];
        }
        for (int i = tid; i < 16 * OUT_DIM; i += 256) {
            int o = i >> 4, k = i & 15;
            Bs[k * 280 + o] = Wr[o * OUT_DIM + kc + k];
        }
        __syncthreads();
#pragma unroll
        for (int ks = 0; ks < 2; ks++) {
            wmma::fragment<wmma::matrix_a, 16, 16, 8, wmma::precision::tf32, wmma::row_major> a0, a1;
            wmma::load_matrix_sync(a0, &As[0 * 16 * 16 + ks * 8], 16);
            wmma::load_matrix_sync(a1, &As[16 * 16 + ks * 8], 16);
#pragma unroll
            for (int i = 0; i < a0.num_elements; i++) {
                a0.x[i] = wmma::__float_to_tf32(a0.x[i]);
                a1.x[i] = wmma::__float_to_tf32(a1.x[i]);
            }
            for (int it = 0; it < ntile; it++) {
                int t  = warp + it * 8;
                int rb = t / 17, cb = t % 17;
                wmma::fragment<wmma::matrix_b, 16, 16, 8, wmma::precision::tf32, wmma::row_major> bfr;
                wmma::load_matrix_sync(bfr, &Bs[ks * 8 * 280 + cb * 16], 280);
#pragma unroll
                for (int i = 0; i < bfr.num_elements; i++) bfr.x[i] = wmma::__float_to_tf32(bfr.x[i]);
                if (rb == 0) wmma::mma_sync(c[it], a0, bfr, c[it]);
                else         wmma::mma_sync(c[it], a1, bfr, c[it]);
            }
        }
        __syncthreads();
    }

    // spill accumulators to smem (Bs/As dead now)
    for (int it = 0; it < ntile; it++) {
        int t  = warp + it * 8;
        int rb = t / 17, cb = t % 17;
        wmma::store_matrix_sync(&outs[(rb * 16) * 280 + cb * 16], c[it], 280, wmma::mem_row_major);
    }
    __syncthreads();

    // fused bias + residual + LayerNorm; warp per row
    for (int rr = warp; rr < 32; rr += 8) {
        int bidx = bm + rr;
        float vals[9];
        float sum = 0.0f, sum2 = 0.0f;
        int cnt = 0;
        for (int o = lane; o < OUT_DIM; o += 32) {
            float x = outs[rr * 280 + o] + br[o];
            x += (o < NODE_DIM) ? node[bidx * NODE_DIM + o]
                                : timef[bidx * TIME_DIM + o - NODE_DIM];
            vals[cnt++] = x;
            sum += x; sum2 += x * x;
        }
#pragma unroll
        for (int off = 16; off; off >>= 1) {
            sum  += __shfl_xor_sync(0xffffffffu, sum, off);
            sum2 += __shfl_xor_sync(0xffffffffu, sum2, off);
        }
        float mu  = sum * (1.0f / OUT_DIM);
        float var = sum2 * (1.0f / OUT_DIM) - mu * mu;
        float rs  = rsqrtf(var + LN_EPS);
        cnt = 0;
        for (int o = lane; o < OUT_DIM; o += 32) {
            out[bidx * OUT_DIM + o] = (vals[cnt++] - mu) * rs * gamma[o] + beta[o];
        }
    }
}

// ---------------------------------------------------------------------------
extern "C" void kernel_launch(void* const* d_in, const int* in_sizes, int n_in,
                              void* d_out, int out_size)
{
    const float* node      = (const float*)d_in[0];
    const float* ntime     = (const float*)d_in[1];   // [B,1,100] -> flat [B,100]
    const float* nbr_node  = (const float*)d_in[2];
    const float* nbr_time  = (const float*)d_in[3];
    const float* nbr_edge  = (const float*)d_in[4];
    const int*   masks     = (const int*)d_in[5];
    const float* Wq        = (const float*)d_in[6];
    const float* Wk        = (const float*)d_in[7];
    const float* Wv        = (const float*)d_in[8];
    const float* Wr        = (const float*)d_in[9];
    const float* br        = (const float*)d_in[10];
    const float* gamma     = (const float*)d_in[11];
    const float* beta      = (const float*)d_in[12];
    float* out = (float*)d_out;

    k1_qproj<<<dim3(BATCH / 64, 5), 256>>>(node, ntime, Wq);
    k2_qk   <<<dim3(BATCH / 64, 7, NH), 256>>>(Wk);
    k3_attn <<<BATCH, 256>>>(nbr_node, nbr_time, nbr_edge, masks);
    k4_ctx  <<<dim3(BATCH / 128, 1, NH), 256>>>(Wv);
    k5_out  <<<BATCH / 32, 256>>>(node, ntime, Wr, br, gamma, beta, out);
}

// round 5
// speedup vs baseline: 1.3423x; 1.3423x over previous
#include <cuda_runtime.h>
#include <mma.h>

using namespace nvcuda;

#define BATCH    16384
#define NODE_DIM 172
#define TIME_DIM 100
#define EDGE_DIM 172
#define OUT_DIM  272
#define KEY_DIM  444
#define KEY_PAD  448
#define BIGN     1792          // 4 * 448
#define NNB      20
#define NH       4
#define DH       68
#define SCALE    0.12126781251816648f  // 68^-0.5
#define LN_EPS   1e-5f

// ---------------- scratch (static device globals) ----------------
__device__ float g_W1 [OUT_DIM * BIGN];    // [272][1792] fused Wq*Wk
__device__ float g_W2 [BIGN * OUT_DIM];    // [1792][272] scattered Wv
__device__ float g_WrT[OUT_DIM * OUT_DIM]; // [272][272]  Wr transposed
__device__ float g_qk [BATCH * BIGN];      // [B][1792]
__device__ float g_z  [BATCH * BIGN];      // [B][1792]
__device__ float g_ctx[BATCH * OUT_DIM];   // [B][272]
__device__ float g_y  [BATCH * OUT_DIM];   // [B][272] pre-LN

// ---------------- cp.async helpers ----------------
__device__ __forceinline__ void cp16(float* dst, const float* src) {
    unsigned d = (unsigned)__cvta_generic_to_shared(dst);
    asm volatile("cp.async.cg.shared.global [%0], [%1], 16;\n" :: "r"(d), "l"(src));
}
__device__ __forceinline__ void cp_commit() {
    asm volatile("cp.async.commit_group;\n");
}
template<int N> __device__ __forceinline__ void cp_wait() {
    asm volatile("cp.async.wait_group %0;\n" :: "n"(N));
}
__device__ __forceinline__ void zfill4(float* dst) {
    *(float4*)dst = make_float4(0.f, 0.f, 0.f, 0.f);
}

// ---------------------------------------------------------------------------
// P1: g_W1[c][h*448+j] = sum_d Wq[h*68+d][c] * Wk[h*68+d][j]   (j>=444 -> 0)
// grid (7 jt, 4 h), 256 threads
// ---------------------------------------------------------------------------
__global__ __launch_bounds__(256) void prep_w1(
    const float* __restrict__ Wq, const float* __restrict__ Wk)
{
    const int jt = blockIdx.x, h = blockIdx.y;
    __shared__ float wk_s[DH][64];
    const int tid = threadIdx.x;
    for (int i = tid; i < DH * 64; i += 256) {
        int d = i >> 6, j = i & 63;
        int gj = jt * 64 + j;
        wk_s[d][j] = (gj < KEY_DIM) ? Wk[(h * DH + d) * KEY_DIM + gj] : 0.0f;
    }
    __syncthreads();
    for (int o = tid; o < OUT_DIM * 64; o += 256) {
        int c = o >> 6, j = o & 63;
        float acc = 0.0f;
#pragma unroll 4
        for (int d = 0; d < DH; d++)
            acc += Wq[(h * DH + d) * OUT_DIM + c] * wk_s[d][j];
        g_W1[(size_t)c * BIGN + h * KEY_PAD + jt * 64 + j] = acc;
    }
}

// P2: g_W2[kk][o] = (kk%448 < 444 && o/68 == kk/448) ? Wv[o][kk%448] : 0
__global__ void prep_w2(const float* __restrict__ Wv)
{
    int kk = blockIdx.x;
    int o  = threadIdx.x;
    if (o < OUT_DIM) {
        int h = kk / KEY_PAD, j = kk % KEY_PAD;
        float v = (j < KEY_DIM && (o / DH) == h) ? Wv[o * KEY_DIM + j] : 0.0f;
        g_W2[(size_t)kk * OUT_DIM + o] = v;
    }
}

// P3: g_WrT[c][o] = Wr[o][c]
__global__ void prep_wrt(const float* __restrict__ Wr)
{
    int c = blockIdx.x;
    int o = threadIdx.x;
    if (o < OUT_DIM)
        g_WrT[c * OUT_DIM + o] = Wr[o * OUT_DIM + c];
}

// ---------------------------------------------------------------------------
// Generic pipelined tf32 GEMM:  C[M=16384][NTOT] = A[M][KTOT] @ Bm[KTOT][NTOT]
// Mtile=128, Ntile=64, Ktile=32, 256 threads, double-buffered cp.async.
// CONCAT: A row = [node(172) | time(100)], KTOT=272.
// grid = (ceil(NTOT/64), M/128) -- n fastest for L2 reuse of A tiles.
// ---------------------------------------------------------------------------
template<int NTOT, int KTOT, bool CONCAT>
__global__ __launch_bounds__(256) void gemm_nn(
    const float* __restrict__ A, const float* __restrict__ A2,
    const float* __restrict__ Bm, float* __restrict__ C)
{
    extern __shared__ float sm[];
    float* As = sm;                  // [2][128][36]
    float* Bs = sm + 2 * 128 * 36;   // [2][32][68]

    const int nt = blockIdx.x, mt = blockIdx.y;
    const int row0 = mt * 128, col0 = nt * 64;
    const int tid = threadIdx.x, warp = tid >> 5;
    const int wm = warp >> 1, wn = warp & 1;
    constexpr int KT = (KTOT + 31) / 32;

    wmma::fragment<wmma::accumulator, 16, 16, 8, float> acc[2][2];
#pragma unroll
    for (int i = 0; i < 2; i++)
#pragma unroll
        for (int j = 0; j < 2; j++) wmma::fill_fragment(acc[i][j], 0.0f);

    auto load_tile = [&](int kt, int buf) {
        float* Ab = As + buf * 128 * 36;
#pragma unroll
        for (int t = 0; t < 4; t++) {
            int idx = tid + t * 256;              // 1024 float4 for A
            int r = idx >> 3, c4 = idx & 7;
            int gk4 = kt * 8 + c4;
            float* dst = Ab + r * 36 + c4 * 4;
            if (CONCAT) {
                if (gk4 < 43)       cp16(dst, A  + ((size_t)(row0 + r) * 43 + gk4) * 4);
                else if (gk4 < 68)  cp16(dst, A2 + ((size_t)(row0 + r) * 25 + (gk4 - 43)) * 4);
                else                zfill4(dst);
            } else {
                if (gk4 * 4 < KTOT) cp16(dst, A + (size_t)(row0 + r) * KTOT + gk4 * 4);
                else                zfill4(dst);
            }
        }
        float* Bb = Bs + buf * 32 * 68;
#pragma unroll
        for (int t = 0; t < 2; t++) {
            int idx = tid + t * 256;              // 512 float4 for B
            int r = idx >> 4, c4 = idx & 15;
            int gk = kt * 32 + r;
            int gc = col0 + c4 * 4;
            float* dst = Bb + r * 68 + c4 * 4;
            if (gk < KTOT && gc < NTOT) cp16(dst, Bm + (size_t)gk * NTOT + gc);
            else                        zfill4(dst);
        }
    };

    load_tile(0, 0);
    cp_commit();

    for (int kt = 0; kt < KT; kt++) {
        if (kt + 1 < KT) {
            load_tile(kt + 1, (kt + 1) & 1);
            cp_commit();
            cp_wait<1>();
        } else {
            cp_wait<0>();
        }
        __syncthreads();

        const float* Ab = As + (kt & 1) * 128 * 36 + wm * 32 * 36;
        const float* Bb = Bs + (kt & 1) * 32 * 68 + wn * 32;
#pragma unroll
        for (int ks = 0; ks < 4; ks++) {
            wmma::fragment<wmma::matrix_a, 16, 16, 8, wmma::precision::tf32, wmma::row_major> a0, a1;
            wmma::fragment<wmma::matrix_b, 16, 16, 8, wmma::precision::tf32, wmma::row_major> b0, b1;
            wmma::load_matrix_sync(a0, Ab + ks * 8, 36);
            wmma::load_matrix_sync(a1, Ab + 16 * 36 + ks * 8, 36);
            wmma::load_matrix_sync(b0, Bb + ks * 8 * 68, 68);
            wmma::load_matrix_sync(b1, Bb + ks * 8 * 68 + 16, 68);
#pragma unroll
            for (int i = 0; i < a0.num_elements; i++) {
                a0.x[i] = wmma::__float_to_tf32(a0.x[i]);
                a1.x[i] = wmma::__float_to_tf32(a1.x[i]);
            }
#pragma unroll
            for (int i = 0; i < b0.num_elements; i++) {
                b0.x[i] = wmma::__float_to_tf32(b0.x[i]);
                b1.x[i] = wmma::__float_to_tf32(b1.x[i]);
            }
            wmma::mma_sync(acc[0][0], a0, b0, acc[0][0]);
            wmma::mma_sync(acc[0][1], a0, b1, acc[0][1]);
            wmma::mma_sync(acc[1][0], a1, b0, acc[1][0]);
            wmma::mma_sync(acc[1][1], a1, b1, acc[1][1]);
        }
        __syncthreads();
    }

#pragma unroll
    for (int i = 0; i < 2; i++)
#pragma unroll
        for (int j = 0; j < 2; j++) {
            int gr = row0 + wm * 32 + i * 16;
            int gc = col0 + wn * 32 + j * 16;
            if (gc < NTOT)   // NTOT % 16 == 0, frag fully in or out
                wmma::store_matrix_sync(C + (size_t)gr * NTOT + gc, acc[i][j],
                                        NTOT, wmma::mem_row_major);
        }
}

// ---------------------------------------------------------------------------
// Attention streaming kernel: one CTA per batch element, float4 everywhere.
// reads qk[B][1792], neighbor features; writes z[B][1792] (pads = 0)
// ---------------------------------------------------------------------------
__global__ __launch_bounds__(256) void attn_kernel(
    const float4* __restrict__ nbr_node4, const float4* __restrict__ nbr_time4,
    const float4* __restrict__ nbr_edge4, const int* __restrict__ masks)
{
    const int b = blockIdx.x;
    __shared__ float4 kv4[NNB][112];   // 35 KB  (443->110 + pad 111)
    __shared__ float4 qk4[NH][112];    // 7 KB
    __shared__ float  prob[NH][NNB];

    const int tid = threadIdx.x;
    const int warp = tid >> 5, lane = tid & 31;

    const float4* np = nbr_node4 + (size_t)b * NNB * 43;
    for (int i = tid; i < NNB * 43; i += 256) kv4[i / 43][i % 43] = np[i];
    const float4* ep = nbr_edge4 + (size_t)b * NNB * 43;
    for (int i = tid; i < NNB * 43; i += 256) kv4[i / 43][43 + i % 43] = ep[i];
    const float4* tp = nbr_time4 + (size_t)b * NNB * 25;
    for (int i = tid; i < NNB * 25; i += 256) kv4[i / 25][86 + i % 25] = tp[i];
    if (tid < NNB) kv4[tid][111] = make_float4(0.f, 0.f, 0.f, 0.f);
    const float4* qp = (const float4*)g_qk + (size_t)b * 448;
    for (int i = tid; i < 448; i += 256) ((float4*)qk4)[i] = qp[i];
    __syncthreads();

    // 80 score dot-products; 10 per warp
    for (int p = warp * 10; p < warp * 10 + 10; p++) {
        int h = p / NNB, n = p % NNB;
        float acc = 0.0f;
#pragma unroll
        for (int t = 0; t < 4; t++) {
            int c = lane + t * 32;
            if (c < 112) {
                float4 q = qk4[h][c], k = kv4[n][c];
                acc += q.x * k.x + q.y * k.y + q.z * k.z + q.w * k.w;
            }
        }
#pragma unroll
        for (int off = 16; off; off >>= 1) acc += __shfl_xor_sync(0xffffffffu, acc, off);
        if (lane == 0)
            prob[h][n] = (masks[b * NNB + n] == 0) ? -1e10f : acc * SCALE;
    }
    __syncthreads();

    if (warp < NH) {
        float s = (lane < NNB) ? prob[warp][lane] : -3.0e38f;
        float m = s;
#pragma unroll
        for (int off = 16; off; off >>= 1) m = fmaxf(m, __shfl_xor_sync(0xffffffffu, m, off));
        float e = (lane < NNB) ? expf(s - m) : 0.0f;
        float sum = e;
#pragma unroll
        for (int off = 16; off; off >>= 1) sum += __shfl_xor_sync(0xffffffffu, sum, off);
        if (lane < NNB) prob[warp][lane] = e / sum;
    }
    __syncthreads();

    float4* zp = (float4*)g_z + (size_t)b * 448;
    for (int i = tid; i < 448; i += 256) {
        int h = i / 112, c = i % 112;
        float4 a = make_float4(0.f, 0.f, 0.f, 0.f);
#pragma unroll
        for (int n = 0; n < NNB; n++) {
            float w = prob[h][n];
            float4 k = kv4[n][c];
            a.x += w * k.x; a.y += w * k.y; a.z += w * k.z; a.w += w * k.w;
        }
        zp[i] = a;
    }
}

// ---------------------------------------------------------------------------
// LN epilogue: x = y + br + residual;  out = (x-mu)*rsqrt(var+eps)*gamma+beta
// 8 rows per CTA (warp per row), float4.
// ---------------------------------------------------------------------------
__global__ __launch_bounds__(256) void ln_kernel(
    const float4* __restrict__ node4, const float4* __restrict__ time4,
    const float4* __restrict__ br4, const float4* __restrict__ g4,
    const float4* __restrict__ be4, float4* __restrict__ out4)
{
    const int warp = threadIdx.x >> 5, lane = threadIdx.x & 31;
    const int b = blockIdx.x * 8 + warp;
    const float4* y4 = (const float4*)g_y;

    float4 v[3];
    float sum = 0.f, sum2 = 0.f;
#pragma unroll
    for (int t = 0; t < 3; t++) {
        int c = lane + t * 32;
        if (c < 68) {
            float4 x = y4[(size_t)b * 68 + c];
            float4 r = (c < 43) ? node4[(size_t)b * 43 + c]
                                : time4[(size_t)b * 25 + (c - 43)];
            float4 bb = br4[c];
            x.x += r.x + bb.x; x.y += r.y + bb.y;
            x.z += r.z + bb.z; x.w += r.w + bb.w;
            v[t] = x;
            sum  += x.x + x.y + x.z + x.w;
            sum2 += x.x * x.x + x.y * x.y + x.z * x.z + x.w * x.w;
        }
    }
#pragma unroll
    for (int off = 16; off; off >>= 1) {
        sum  += __shfl_xor_sync(0xffffffffu, sum,  off);
        sum2 += __shfl_xor_sync(0xffffffffu, sum2, off);
    }
    const float mu = sum * (1.0f / OUT_DIM);
    const float var = sum2 * (1.0f / OUT_DIM) - mu * mu;
    const float rs = rsqrtf(var + LN_EPS);
#pragma unroll
    for (int t = 0; t < 3; t++) {
        int c = lane + t * 32;
        if (c < 68) {
            float4 gg = g4[c], be = be4[c];
            float4 o;
            o.x = (v[t].x - mu) * rs * gg.x + be.x;
            o.y = (v[t].y - mu) * rs * gg.y + be.y;
            o.z = (v[t].z - mu) * rs * gg.z + be.z;
            o.w = (v[t].w - mu) * rs * gg.w + be.w;
            out4[(size_t)b * 68 + c] = o;
        }
    }
}

// ---------------------------------------------------------------------------
extern "C" void kernel_launch(void* const* d_in, const int* in_sizes, int n_in,
                              void* d_out, int out_size)
{
    const float* node     = (const float*)d_in[0];
    const float* ntime    = (const float*)d_in[1];
    const float* nbr_node = (const float*)d_in[2];
    const float* nbr_time = (const float*)d_in[3];
    const float* nbr_edge = (const float*)d_in[4];
    const int*   masks    = (const int*)d_in[5];
    const float* Wq       = (const float*)d_in[6];
    const float* Wk       = (const float*)d_in[7];
    const float* Wv       = (const float*)d_in[8];
    const float* Wr       = (const float*)d_in[9];
    const float* br       = (const float*)d_in[10];
    const float* gamma    = (const float*)d_in[11];
    const float* beta     = (const float*)d_in[12];
    float* out = (float*)d_out;

    const int SMEMSZ = (2 * 128 * 36 + 2 * 32 * 68) * 4;   // 54272 B

    cudaFuncSetAttribute(gemm_nn<BIGN,   OUT_DIM, true >,
                         cudaFuncAttributeMaxDynamicSharedMemorySize, SMEMSZ);
    cudaFuncSetAttribute(gemm_nn<OUT_DIM, BIGN,   false>,
                         cudaFuncAttributeMaxDynamicSharedMemorySize, SMEMSZ);
    cudaFuncSetAttribute(gemm_nn<OUT_DIM, OUT_DIM, false>,
                         cudaFuncAttributeMaxDynamicSharedMemorySize, SMEMSZ);

    float* g_W1p, * g_W2p, * g_WrTp, * g_qkp, * g_zp, * g_ctxp, * g_yp;
    cudaGetSymbolAddress((void**)&g_W1p,  g_W1);
    cudaGetSymbolAddress((void**)&g_W2p,  g_W2);
    cudaGetSymbolAddress((void**)&g_WrTp, g_WrT);
    cudaGetSymbolAddress((void**)&g_qkp,  g_qk);
    cudaGetSymbolAddress((void**)&g_zp,   g_z);
    cudaGetSymbolAddress((void**)&g_ctxp, g_ctx);
    cudaGetSymbolAddress((void**)&g_yp,   g_y);

    // prep fused weights (tiny)
    prep_w1 <<<dim3(7, NH), 256>>>(Wq, Wk);
    prep_w2 <<<BIGN, 288>>>(Wv);
    prep_wrt<<<OUT_DIM, 288>>>(Wr);

    // qk = q_in @ W1   [B,1792]
    gemm_nn<BIGN, OUT_DIM, true>
        <<<dim3(BIGN / 64, BATCH / 128), 256, SMEMSZ>>>(node, ntime, g_W1p, g_qkp);

    // streaming attention -> z [B,1792]
    attn_kernel<<<BATCH, 256>>>((const float4*)nbr_node, (const float4*)nbr_time,
                                (const float4*)nbr_edge, masks);

    // ctx = z @ W2   [B,272]
    gemm_nn<OUT_DIM, BIGN, false>
        <<<dim3(5, BATCH / 128), 256, SMEMSZ>>>(g_zp, nullptr, g_W2p, g_ctxp);

    // y = ctx @ WrT  [B,272]
    gemm_nn<OUT_DIM, OUT_DIM, false>
        <<<dim3(5, BATCH / 128), 256, SMEMSZ>>>(g_ctxp, nullptr, g_WrTp, g_yp);

    // LN(y + br + residual)
    ln_kernel<<<BATCH / 8, 256>>>((const float4*)node, (const float4*)ntime,
                                  (const float4*)br, (const float4*)gamma,
                                  (const float4*)beta, (float4*)out);
}

// round 6
// speedup vs baseline: 2.4061x; 1.7925x over previous
#include <cuda_runtime.h>
#include <mma.h>

using namespace nvcuda;

#define BATCH    16384
#define NODE_DIM 172
#define TIME_DIM 100
#define OUT_DIM  272
#define KEY_DIM  444
#define KEY_PAD  448
#define BIGN     1792          // 4 * 448
#define CTXP     320           // 4 * 80
#define NNB      20
#define NH       4
#define DH       68
#define SCALE    0.12126781251816648f  // 68^-0.5
#define LN_EPS   1e-5f

// ---------------- scratch (static device globals) ----------------
__device__ float g_qin [BATCH * OUT_DIM];     // rounded [B,272] = [node|time]
__device__ float g_q   [BATCH * OUT_DIM];     // rounded q
__device__ float g_qk  [BATCH * BIGN];        // [B,4,448]
__device__ float g_z   [BATCH * BIGN];        // rounded, pads 0
__device__ float g_ctx [BATCH * CTXP];        // rounded [B,4,80], pads 0
__device__ float g_y   [BATCH * OUT_DIM];     // pre-LN
// pre-rounded weights
__device__ float g_W1q [OUT_DIM * OUT_DIM];   // Wq^T
__device__ float g_Wkp [NH * DH * KEY_PAD];   // [4][68][448], col pads 0
__device__ float g_Wvp [NH * KEY_PAD * 80];   // [4][448][80], pads 0
__device__ float g_W3  [CTXP * OUT_DIM];      // [320][272] Wr^T scattered

// ---------------- helpers ----------------
__device__ __forceinline__ float rnd_tf32(float x) {
    float r; asm("cvt.rna.tf32.f32 %0, %1;" : "=f"(r) : "f"(x)); return r;
}
__device__ __forceinline__ void cp16(float* dst, const float* src) {
    unsigned d = (unsigned)__cvta_generic_to_shared(dst);
    asm volatile("cp.async.cg.shared.global [%0], [%1], 16;\n" :: "r"(d), "l"(src));
}
__device__ __forceinline__ void cp_commit() {
    asm volatile("cp.async.commit_group;\n");
}
template<int N> __device__ __forceinline__ void cp_wait() {
    asm volatile("cp.async.wait_group %0;\n" :: "n"(N));
}
__device__ __forceinline__ void zfill4(float* dst) {
    *(float4*)dst = make_float4(0.f, 0.f, 0.f, 0.f);
}

// ---------------------------------------------------------------------------
// prep kernels (tiny, off hot path)
// ---------------------------------------------------------------------------
__global__ void prep_qin(const float4* __restrict__ node4,
                         const float4* __restrict__ time4)
{
    int i = blockIdx.x * 256 + threadIdx.x;           // over B*68 float4
    if (i >= BATCH * 68) return;
    int b = i / 68, c = i % 68;
    float4 v = (c < 43) ? node4[(size_t)b * 43 + c] : time4[(size_t)b * 25 + (c - 43)];
    v.x = rnd_tf32(v.x); v.y = rnd_tf32(v.y); v.z = rnd_tf32(v.z); v.w = rnd_tf32(v.w);
    ((float4*)g_qin)[i] = v;
}
__global__ void prep_w1q(const float* __restrict__ Wq) {
    int c = blockIdx.x, o = threadIdx.x;
    g_W1q[c * OUT_DIM + o] = rnd_tf32(Wq[o * OUT_DIM + c]);
}
__global__ void prep_wk(const float* __restrict__ Wk) {
    int d = blockIdx.x, h = blockIdx.y, j = threadIdx.x;
    float v = (j < KEY_DIM) ? rnd_tf32(Wk[(h * DH + d) * KEY_DIM + j]) : 0.0f;
    g_Wkp[(h * DH + d) * KEY_PAD + j] = v;
}
__global__ void prep_wv(const float* __restrict__ Wv) {
    int j = blockIdx.x, h = blockIdx.y, d = threadIdx.x;
    float v = (j < KEY_DIM && d < DH) ? rnd_tf32(Wv[(h * DH + d) * KEY_DIM + j]) : 0.0f;
    g_Wvp[(h * KEY_PAD + j) * 80 + d] = v;
}
__global__ void prep_w3(const float* __restrict__ Wr) {
    int kk = blockIdx.x, o = threadIdx.x;            // kk = h*80+d
    int h = kk / 80, d = kk % 80;
    float v = (d < DH) ? rnd_tf32(Wr[o * OUT_DIM + h * DH + d]) : 0.0f;
    g_W3[kk * OUT_DIM + o] = v;
}

// ---------------------------------------------------------------------------
// Generic pipelined tf32 GEMM (all operands pre-rounded -> no cvt in loop):
//   C[m, n] = sum_k A[m*lda + k] * Bm[k*ldb + n]   for m in 128-tile, n in 64-tile
// grid = (ceil(NTOT/64), M/128, heads); per-head offsets sA/sB/sC.
// ROUND_C: round accumulators to tf32 before store (producer-side rounding).
// ---------------------------------------------------------------------------
template<int NTOT, int KACT, bool ROUND_C>
__global__ __launch_bounds__(256) void gemm_nn(
    const float* __restrict__ A, int lda, int sA,
    const float* __restrict__ Bm, int ldb, int sB,
    float* __restrict__ C, int ldc, int sC)
{
    extern __shared__ float sm[];
    float* As = sm;                  // [2][128][36]
    float* Bs = sm + 2 * 128 * 36;   // [2][32][68]

    A  += (size_t)blockIdx.z * sA;
    Bm += (size_t)blockIdx.z * sB;
    C  += (size_t)blockIdx.z * sC;

    const int nt = blockIdx.x, mt = blockIdx.y;
    const int row0 = mt * 128, col0 = nt * 64;
    const int tid = threadIdx.x, warp = tid >> 5;
    const int wm = warp >> 1, wn = warp & 1;
    constexpr int KT = (KACT + 31) / 32;
    constexpr int KMAX4 = (KACT + 3) / 4;

    wmma::fragment<wmma::accumulator, 16, 16, 8, float> acc[2][2];
#pragma unroll
    for (int i = 0; i < 2; i++)
#pragma unroll
        for (int j = 0; j < 2; j++) wmma::fill_fragment(acc[i][j], 0.0f);

    auto load_tile = [&](int kt, int buf) {
        float* Ab = As + buf * 128 * 36;
#pragma unroll
        for (int t = 0; t < 4; t++) {
            int idx = tid + t * 256;              // 1024 float4 for A
            int r = idx >> 3, c4 = idx & 7;
            int gk4 = kt * 8 + c4;
            float* dst = Ab + r * 36 + c4 * 4;
            if (gk4 < KMAX4) cp16(dst, A + (size_t)(row0 + r) * lda + gk4 * 4);
            else             zfill4(dst);
        }
        float* Bb = Bs + buf * 32 * 68;
#pragma unroll
        for (int t = 0; t < 2; t++) {
            int idx = tid + t * 256;              // 512 float4 for B
            int r = idx >> 4, c4 = idx & 15;
            int gk = kt * 32 + r;
            int gc = col0 + c4 * 4;
            float* dst = Bb + r * 68 + c4 * 4;
            if (gk < KACT && gc < NTOT) cp16(dst, Bm + (size_t)gk * ldb + gc);
            else                        zfill4(dst);
        }
    };

    load_tile(0, 0);
    cp_commit();

    for (int kt = 0; kt < KT; kt++) {
        if (kt + 1 < KT) {
            load_tile(kt + 1, (kt + 1) & 1);
            cp_commit();
            cp_wait<1>();
        } else {
            cp_wait<0>();
        }
        __syncthreads();

        const float* Ab = As + (kt & 1) * 128 * 36 + wm * 32 * 36;
        const float* Bb = Bs + (kt & 1) * 32 * 68 + wn * 32;
#pragma unroll
        for (int ks = 0; ks < 4; ks++) {
            wmma::fragment<wmma::matrix_a, 16, 16, 8, wmma::precision::tf32, wmma::row_major> a0, a1;
            wmma::fragment<wmma::matrix_b, 16, 16, 8, wmma::precision::tf32, wmma::row_major> b0, b1;
            wmma::load_matrix_sync(a0, Ab + ks * 8, 36);
            wmma::load_matrix_sync(a1, Ab + 16 * 36 + ks * 8, 36);
            wmma::load_matrix_sync(b0, Bb + ks * 8 * 68, 68);
            wmma::load_matrix_sync(b1, Bb + ks * 8 * 68 + 16, 68);
            wmma::mma_sync(acc[0][0], a0, b0, acc[0][0]);
            wmma::mma_sync(acc[0][1], a0, b1, acc[0][1]);
            wmma::mma_sync(acc[1][0], a1, b0, acc[1][0]);
            wmma::mma_sync(acc[1][1], a1, b1, acc[1][1]);
        }
        __syncthreads();
    }

#pragma unroll
    for (int i = 0; i < 2; i++)
#pragma unroll
        for (int j = 0; j < 2; j++) {
            int gr = row0 + wm * 32 + i * 16;
            int gc = col0 + wn * 32 + j * 16;
            if (gc < NTOT) {
                if (ROUND_C) {
#pragma unroll
                    for (int e = 0; e < acc[i][j].num_elements; e++)
                        acc[i][j].x[e] = rnd_tf32(acc[i][j].x[e]);
                }
                wmma::store_matrix_sync(C + (size_t)gr * ldc + gc, acc[i][j],
                                        ldc, wmma::mem_row_major);
            }
        }
}

// ---------------------------------------------------------------------------
// Attention streaming kernel: one CTA per batch element, float4 everywhere.
// reads qk[B][1792], neighbor features; writes z[B][1792] rounded (pads = 0)
// ---------------------------------------------------------------------------
__global__ __launch_bounds__(256) void attn_kernel(
    const float4* __restrict__ nbr_node4, const float4* __restrict__ nbr_time4,
    const float4* __restrict__ nbr_edge4, const int* __restrict__ masks)
{
    const int b = blockIdx.x;
    __shared__ float4 kv4[NNB][112];   // 35 KB
    __shared__ float4 qk4[NH][112];    // 7 KB
    __shared__ float  prob[NH][NNB];

    const int tid = threadIdx.x;
    const int warp = tid >> 5, lane = tid & 31;

    const float4* np = nbr_node4 + (size_t)b * NNB * 43;
    for (int i = tid; i < NNB * 43; i += 256) kv4[i / 43][i % 43] = np[i];
    const float4* ep = nbr_edge4 + (size_t)b * NNB * 43;
    for (int i = tid; i < NNB * 43; i += 256) kv4[i / 43][43 + i % 43] = ep[i];
    const float4* tp = nbr_time4 + (size_t)b * NNB * 25;
    for (int i = tid; i < NNB * 25; i += 256) kv4[i / 25][86 + i % 25] = tp[i];
    if (tid < NNB) kv4[tid][111] = make_float4(0.f, 0.f, 0.f, 0.f);
    const float4* qp = (const float4*)g_qk + (size_t)b * 448;
    for (int i = tid; i < 448; i += 256) ((float4*)qk4)[i] = qp[i];
    __syncthreads();

    // 80 score dot-products; 10 per warp
    for (int p = warp * 10; p < warp * 10 + 10; p++) {
        int h = p / NNB, n = p % NNB;
        float acc = 0.0f;
#pragma unroll
        for (int t = 0; t < 4; t++) {
            int c = lane + t * 32;
            if (c < 112) {
                float4 q = qk4[h][c], k = kv4[n][c];
                acc += q.x * k.x + q.y * k.y + q.z * k.z + q.w * k.w;
            }
        }
#pragma unroll
        for (int off = 16; off; off >>= 1) acc += __shfl_xor_sync(0xffffffffu, acc, off);
        if (lane == 0)
            prob[h][n] = (masks[b * NNB + n] == 0) ? -1e10f : acc * SCALE;
    }
    __syncthreads();

    if (warp < NH) {
        float s = (lane < NNB) ? prob[warp][lane] : -3.0e38f;
        float m = s;
#pragma unroll
        for (int off = 16; off; off >>= 1) m = fmaxf(m, __shfl_xor_sync(0xffffffffu, m, off));
        float e = (lane < NNB) ? expf(s - m) : 0.0f;
        float sum = e;
#pragma unroll
        for (int off = 16; off; off >>= 1) sum += __shfl_xor_sync(0xffffffffu, sum, off);
        if (lane < NNB) prob[warp][lane] = e / sum;
    }
    __syncthreads();

    float4* zp = (float4*)g_z + (size_t)b * 448;
    for (int i = tid; i < 448; i += 256) {
        int h = i / 112, c = i % 112;
        float4 a = make_float4(0.f, 0.f, 0.f, 0.f);
#pragma unroll
        for (int n = 0; n < NNB; n++) {
            float w = prob[h][n];
            float4 k = kv4[n][c];
            a.x += w * k.x; a.y += w * k.y; a.z += w * k.z; a.w += w * k.w;
        }
        a.x = rnd_tf32(a.x); a.y = rnd_tf32(a.y);
        a.z = rnd_tf32(a.z); a.w = rnd_tf32(a.w);
        zp[i] = a;
    }
}

// ---------------------------------------------------------------------------
// LN epilogue: x = y + br + residual;  out = (x-mu)*rsqrt(var+eps)*gamma+beta
// ---------------------------------------------------------------------------
__global__ __launch_bounds__(256) void ln_kernel(
    const float4* __restrict__ node4, const float4* __restrict__ time4,
    const float4* __restrict__ br4, const float4* __restrict__ g4,
    const float4* __restrict__ be4, float4* __restrict__ out4)
{
    const int warp = threadIdx.x >> 5, lane = threadIdx.x & 31;
    const int b = blockIdx.x * 8 + warp;
    const float4* y4 = (const float4*)g_y;

    float4 v[3];
    float sum = 0.f, sum2 = 0.f;
#pragma unroll
    for (int t = 0; t < 3; t++) {
        int c = lane + t * 32;
        if (c < 68) {
            float4 x = y4[(size_t)b * 68 + c];
            float4 r = (c < 43) ? node4[(size_t)b * 43 + c]
                                : time4[(size_t)b * 25 + (c - 43)];
            float4 bb = br4[c];
            x.x += r.x + bb.x; x.y += r.y + bb.y;
            x.z += r.z + bb.z; x.w += r.w + bb.w;
            v[t] = x;
            sum  += x.x + x.y + x.z + x.w;
            sum2 += x.x * x.x + x.y * x.y + x.z * x.z + x.w * x.w;
        }
    }
#pragma unroll
    for (int off = 16; off; off >>= 1) {
        sum  += __shfl_xor_sync(0xffffffffu, sum,  off);
        sum2 += __shfl_xor_sync(0xffffffffu, sum2, off);
    }
    const float mu = sum * (1.0f / OUT_DIM);
    const float var = sum2 * (1.0f / OUT_DIM) - mu * mu;
    const float rs = rsqrtf(var + LN_EPS);
#pragma unroll
    for (int t = 0; t < 3; t++) {
        int c = lane + t * 32;
        if (c < 68) {
            float4 gg = g4[c], be = be4[c];
            float4 o;
            o.x = (v[t].x - mu) * rs * gg.x + be.x;
            o.y = (v[t].y - mu) * rs * gg.y + be.y;
            o.z = (v[t].z - mu) * rs * gg.z + be.z;
            o.w = (v[t].w - mu) * rs * gg.w + be.w;
            out4[(size_t)b * 68 + c] = o;
        }
    }
}

// ---------------------------------------------------------------------------
extern "C" void kernel_launch(void* const* d_in, const int* in_sizes, int n_in,
                              void* d_out, int out_size)
{
    const float* node     = (const float*)d_in[0];
    const float* ntime    = (const float*)d_in[1];
    const float* nbr_node = (const float*)d_in[2];
    const float* nbr_time = (const float*)d_in[3];
    const float* nbr_edge = (const float*)d_in[4];
    const int*   masks    = (const int*)d_in[5];
    const float* Wq       = (const float*)d_in[6];
    const float* Wk       = (const float*)d_in[7];
    const float* Wv       = (const float*)d_in[8];
    const float* Wr       = (const float*)d_in[9];
    const float* br       = (const float*)d_in[10];
    const float* gamma    = (const float*)d_in[11];
    const float* beta     = (const float*)d_in[12];
    float* out = (float*)d_out;

    const int SMEMSZ = (2 * 128 * 36 + 2 * 32 * 68) * 4;   // 54272 B

    cudaFuncSetAttribute(gemm_nn<OUT_DIM, OUT_DIM, true >,
                         cudaFuncAttributeMaxDynamicSharedMemorySize, SMEMSZ);
    cudaFuncSetAttribute(gemm_nn<KEY_PAD, DH,      false>,
                         cudaFuncAttributeMaxDynamicSharedMemorySize, SMEMSZ);
    cudaFuncSetAttribute(gemm_nn<80,      KEY_PAD, true >,
                         cudaFuncAttributeMaxDynamicSharedMemorySize, SMEMSZ);
    cudaFuncSetAttribute(gemm_nn<OUT_DIM, CTXP,    false>,
                         cudaFuncAttributeMaxDynamicSharedMemorySize, SMEMSZ);

    float *g_qinp, *g_qp, *g_qkp, *g_zp, *g_ctxp, *g_yp;
    float *g_W1qp, *g_Wkpp, *g_Wvpp, *g_W3p;
    cudaGetSymbolAddress((void**)&g_qinp, g_qin);
    cudaGetSymbolAddress((void**)&g_qp,   g_q);
    cudaGetSymbolAddress((void**)&g_qkp,  g_qk);
    cudaGetSymbolAddress((void**)&g_zp,   g_z);
    cudaGetSymbolAddress((void**)&g_ctxp, g_ctx);
    cudaGetSymbolAddress((void**)&g_yp,   g_y);
    cudaGetSymbolAddress((void**)&g_W1qp, g_W1q);
    cudaGetSymbolAddress((void**)&g_Wkpp, g_Wkp);
    cudaGetSymbolAddress((void**)&g_Wvpp, g_Wvp);
    cudaGetSymbolAddress((void**)&g_W3p,  g_W3);

    // preps
    prep_qin<<<(BATCH * 68 + 255) / 256, 256>>>((const float4*)node, (const float4*)ntime);
    prep_w1q<<<OUT_DIM, OUT_DIM>>>(Wq);
    prep_wk <<<dim3(DH, NH), KEY_PAD>>>(Wk);
    prep_wv <<<dim3(KEY_PAD, NH), 80>>>(Wv);
    prep_w3 <<<CTXP, OUT_DIM>>>(Wr);

    // q = qin @ Wq^T     [B,272]
    gemm_nn<OUT_DIM, OUT_DIM, true>
        <<<dim3(5, BATCH / 128, 1), 256, SMEMSZ>>>(
            g_qinp, OUT_DIM, 0, g_W1qp, OUT_DIM, 0, g_qp, OUT_DIM, 0);

    // qk_h = q_h @ Wk_h  [B,4,448]
    gemm_nn<KEY_PAD, DH, false>
        <<<dim3(7, BATCH / 128, NH), 256, SMEMSZ>>>(
            g_qp, OUT_DIM, DH, g_Wkpp, KEY_PAD, DH * KEY_PAD, g_qkp, BIGN, KEY_PAD);

    // streaming attention -> z [B,1792]
    attn_kernel<<<BATCH, 256>>>((const float4*)nbr_node, (const float4*)nbr_time,
                                (const float4*)nbr_edge, masks);

    // ctx_h = z_h @ Wv_h^T  [B,4,80]
    gemm_nn<80, KEY_PAD, true>
        <<<dim3(2, BATCH / 128, NH), 256, SMEMSZ>>>(
            g_zp, BIGN, KEY_PAD, g_Wvpp, 80, KEY_PAD * 80, g_ctxp, CTXP, 80);

    // y = ctxp @ W3   [B,272]
    gemm_nn<OUT_DIM, CTXP, false>
        <<<dim3(5, BATCH / 128, 1), 256, SMEMSZ>>>(
            g_ctxp, CTXP, 0, g_W3p, OUT_DIM, 0, g_yp, OUT_DIM, 0);

    // LN(y + br + residual)
    ln_kernel<<<BATCH / 8, 256>>>((const float4*)node, (const float4*)ntime,
                                  (const float4*)br, (const float4*)gamma,
                                  (const float4*)beta, (float4*)out);
}

// round 8
// speedup vs baseline: 2.7249x; 1.1325x over previous
#include <cuda_runtime.h>
#include <mma.h>

using namespace nvcuda;

#define BATCH    16384
#define NODE_DIM 172
#define TIME_DIM 100
#define OUT_DIM  272
#define KEY_DIM  444
#define KEY_PAD  448
#define BIGN     1792          // 4 * 448
#define CTXP     320           // 4 * 80
#define NNB      20
#define NH       4
#define DH       68
#define SCALE    0.12126781251816648f  // 68^-0.5
#define LN_EPS   1e-5f

// ---------------- scratch (static device globals) ----------------
__device__ float g_qin [BATCH * OUT_DIM];     // rounded [B,272] = [node|time]
__device__ float g_q   [BATCH * OUT_DIM];     // rounded q
__device__ float g_qk  [BATCH * BIGN];        // [B,4,448]
__device__ float g_z   [BATCH * BIGN];        // rounded, pads 0
__device__ float g_ctx [BATCH * CTXP];        // rounded [B,4,80], pads 0
__device__ float g_y   [BATCH * OUT_DIM];     // pre-LN
// pre-rounded weights
__device__ float g_W1q [OUT_DIM * OUT_DIM];   // Wq^T
__device__ float g_Wkp [NH * DH * KEY_PAD];   // [4][68][448], col pads 0
__device__ float g_Wvp [NH * KEY_PAD * 80];   // [4][448][80], pads 0
__device__ float g_W3  [CTXP * OUT_DIM];      // [320][272] Wr^T scattered

// ---------------- helpers ----------------
__device__ __forceinline__ float rnd_tf32(float x) {
    float r; asm("cvt.rna.tf32.f32 %0, %1;" : "=f"(r) : "f"(x)); return r;
}
__device__ __forceinline__ void cp16(void* dst, const void* src) {
    unsigned d = (unsigned)__cvta_generic_to_shared(dst);
    asm volatile("cp.async.cg.shared.global [%0], [%1], 16;\n" :: "r"(d), "l"(src));
}
__device__ __forceinline__ void cp_commit() {
    asm volatile("cp.async.commit_group;\n");
}
template<int N> __device__ __forceinline__ void cp_wait() {
    asm volatile("cp.async.wait_group %0;\n" :: "n"(N));
}
__device__ __forceinline__ void zfill4(float* dst) {
    *(float4*)dst = make_float4(0.f, 0.f, 0.f, 0.f);
}

// ---------------------------------------------------------------------------
// prep kernels
// ---------------------------------------------------------------------------
__global__ void prep_qin(const float4* __restrict__ node4,
                         const float4* __restrict__ time4)
{
    int i = blockIdx.x * 256 + threadIdx.x;           // over B*68 float4
    if (i >= BATCH * 68) return;
    int b = i / 68, c = i % 68;
    float4 v = (c < 43) ? node4[(size_t)b * 43 + c] : time4[(size_t)b * 25 + (c - 43)];
    v.x = rnd_tf32(v.x); v.y = rnd_tf32(v.y); v.z = rnd_tf32(v.z); v.w = rnd_tf32(v.w);
    ((float4*)g_qin)[i] = v;
}

// all four weight preps in one launch
#define PW_N1 (OUT_DIM * OUT_DIM)        // w1q    73984
#define PW_N2 (NH * DH * KEY_PAD)        // wk    121856
#define PW_N3 (NH * KEY_PAD * 80)        // wv    143360
#define PW_N4 (CTXP * OUT_DIM)           // w3     87040
#define PW_TOT (PW_N1 + PW_N2 + PW_N3 + PW_N4)
__global__ void prep_weights(const float* __restrict__ Wq, const float* __restrict__ Wk,
                             const float* __restrict__ Wv, const float* __restrict__ Wr)
{
    int idx = blockIdx.x * 256 + threadIdx.x;
    if (idx < PW_N1) {
        int c = idx / OUT_DIM, o = idx % OUT_DIM;
        g_W1q[c * OUT_DIM + o] = rnd_tf32(Wq[o * OUT_DIM + c]);
    } else if (idx < PW_N1 + PW_N2) {
        int i2 = idx - PW_N1;
        int hd = i2 / KEY_PAD, j = i2 % KEY_PAD;     // hd = h*68+d
        g_Wkp[hd * KEY_PAD + j] = (j < KEY_DIM) ? rnd_tf32(Wk[hd * KEY_DIM + j]) : 0.0f;
    } else if (idx < PW_N1 + PW_N2 + PW_N3) {
        int i3 = idx - PW_N1 - PW_N2;
        int hj = i3 / 80, d = i3 % 80;
        int h = hj / KEY_PAD, j = hj % KEY_PAD;
        float v = (j < KEY_DIM && d < DH) ? rnd_tf32(Wv[(h * DH + d) * KEY_DIM + j]) : 0.0f;
        g_Wvp[hj * 80 + d] = v;
    } else if (idx < PW_TOT) {
        int i4 = idx - PW_N1 - PW_N2 - PW_N3;
        int kk = i4 / OUT_DIM, o = i4 % OUT_DIM;
        int h = kk / 80, d = kk % 80;
        g_W3[kk * OUT_DIM + o] = (d < DH) ? rnd_tf32(Wr[o * OUT_DIM + h * DH + d]) : 0.0f;
    }
}

// ---------------------------------------------------------------------------
// 3-stage cp.async tf32 GEMM, one __syncthreads per K-tile, exact-K tail:
//   C[m, n] = sum_k A[m*lda + k] * Bm[k*ldb + n]
// Mtile=128, Ntile=64, Ktile=32. grid = (ceil(NTOT/64), M/128, heads).
// ---------------------------------------------------------------------------
template<int NTOT, int KACT, bool ROUND_C>
__global__ __launch_bounds__(256) void gemm_nn(
    const float* __restrict__ A, int lda, int sA,
    const float* __restrict__ Bm, int ldb, int sB,
    float* __restrict__ C, int ldc, int sC)
{
    extern __shared__ float sm[];
    float* As = sm;                  // [3][128][36]
    float* Bs = sm + 3 * 128 * 36;   // [3][32][68]

    A  += (size_t)blockIdx.z * sA;
    Bm += (size_t)blockIdx.z * sB;
    C  += (size_t)blockIdx.z * sC;

    const int nt = blockIdx.x, mt = blockIdx.y;
    const int row0 = mt * 128, col0 = nt * 64;
    const int tid = threadIdx.x, warp = tid >> 5;
    const int wm = warp >> 1, wn = warp & 1;
    constexpr int KT    = (KACT + 31) / 32;
    constexpr int KMAX4 = (KACT + 3) / 4;
    constexpr int REM   = KACT - 32 * (KT - 1);
    constexpr int TAIL  = (REM + 7) / 8;          // mma steps in last K-tile

    wmma::fragment<wmma::accumulator, 16, 16, 8, float> acc[2][2];
#pragma unroll
    for (int i = 0; i < 2; i++)
#pragma unroll
        for (int j = 0; j < 2; j++) wmma::fill_fragment(acc[i][j], 0.0f);

    auto load_tile = [&](int kt, int buf) {
        float* Ab = As + buf * 128 * 36;
#pragma unroll
        for (int t = 0; t < 4; t++) {
            int idx = tid + t * 256;              // 1024 float4 for A
            int r = idx >> 3, c4 = idx & 7;
            int gk4 = kt * 8 + c4;
            float* dst = Ab + r * 36 + c4 * 4;
            if (gk4 < KMAX4) cp16(dst, A + (size_t)(row0 + r) * lda + gk4 * 4);
            else             zfill4(dst);
        }
        float* Bb = Bs + buf * 32 * 68;
#pragma unroll
        for (int t = 0; t < 2; t++) {
            int idx = tid + t * 256;              // 512 float4 for B
            int r = idx >> 4, c4 = idx & 15;
            int gk = kt * 32 + r;
            int gc = col0 + c4 * 4;
            float* dst = Bb + r * 68 + c4 * 4;
            if (gk < KACT && gc < NTOT) cp16(dst, Bm + (size_t)gk * ldb + gc);
            else                        zfill4(dst);
        }
    };

    // prologue: 2 stages in flight
    load_tile(0, 0); cp_commit();
    load_tile(1, 1); cp_commit();

    // main loop (full 4-step tiles)
    for (int kt = 0; kt < KT - 1; kt++) {
        cp_wait<1>();            // buf kt%3 ready (oldest of the <=2 pending)
        __syncthreads();         // everyone done reading buf (kt-1)%3 == (kt+2)%3
        if (kt + 2 < KT) { load_tile(kt + 2, (kt + 2) % 3); cp_commit(); }

        const float* Ab = As + (kt % 3) * 128 * 36 + wm * 32 * 36;
        const float* Bb = Bs + (kt % 3) * 32 * 68 + wn * 32;
#pragma unroll
        for (int ks = 0; ks < 4; ks++) {
            wmma::fragment<wmma::matrix_a, 16, 16, 8, wmma::precision::tf32, wmma::row_major> a0, a1;
            wmma::fragment<wmma::matrix_b, 16, 16, 8, wmma::precision::tf32, wmma::row_major> b0, b1;
            wmma::load_matrix_sync(a0, Ab + ks * 8, 36);
            wmma::load_matrix_sync(a1, Ab + 16 * 36 + ks * 8, 36);
            wmma::load_matrix_sync(b0, Bb + ks * 8 * 68, 68);
            wmma::load_matrix_sync(b1, Bb + ks * 8 * 68 + 16, 68);
            wmma::mma_sync(acc[0][0], a0, b0, acc[0][0]);
            wmma::mma_sync(acc[0][1], a0, b1, acc[0][1]);
            wmma::mma_sync(acc[1][0], a1, b0, acc[1][0]);
            wmma::mma_sync(acc[1][1], a1, b1, acc[1][1]);
        }
    }

    // last tile: TAIL steps only
    {
        const int kt = KT - 1;
        cp_wait<0>();
        __syncthreads();
        const float* Ab = As + (kt % 3) * 128 * 36 + wm * 32 * 36;
        const float* Bb = Bs + (kt % 3) * 32 * 68 + wn * 32;
#pragma unroll
        for (int ks = 0; ks < TAIL; ks++) {
            wmma::fragment<wmma::matrix_a, 16, 16, 8, wmma::precision::tf32, wmma::row_major> a0, a1;
            wmma::fragment<wmma::matrix_b, 16, 16, 8, wmma::precision::tf32, wmma::row_major> b0, b1;
            wmma::load_matrix_sync(a0, Ab + ks * 8, 36);
            wmma::load_matrix_sync(a1, Ab + 16 * 36 + ks * 8, 36);
            wmma::load_matrix_sync(b0, Bb + ks * 8 * 68, 68);
            wmma::load_matrix_sync(b1, Bb + ks * 8 * 68 + 16, 68);
            wmma::mma_sync(acc[0][0], a0, b0, acc[0][0]);
            wmma::mma_sync(acc[0][1], a0, b1, acc[0][1]);
            wmma::mma_sync(acc[1][0], a1, b0, acc[1][0]);
            wmma::mma_sync(acc[1][1], a1, b1, acc[1][1]);
        }
    }

#pragma unroll
    for (int i = 0; i < 2; i++)
#pragma unroll
        for (int j = 0; j < 2; j++) {
            int gr = row0 + wm * 32 + i * 16;
            int gc = col0 + wn * 32 + j * 16;
            if (gc < NTOT) {
                if (ROUND_C) {
#pragma unroll
                    for (int e = 0; e < acc[i][j].num_elements; e++)
                        acc[i][j].x[e] = rnd_tf32(acc[i][j].x[e]);
                }
                wmma::store_matrix_sync(C + (size_t)gr * ldc + gc, acc[i][j],
                                        ldc, wmma::mem_row_major);
            }
        }
}

// ---------------------------------------------------------------------------
// Attention streaming kernel: one CTA per batch element, cp.async loads.
// reads qk[B][1792], neighbor features; writes z[B][1792] rounded (pads = 0)
// ---------------------------------------------------------------------------
__global__ __launch_bounds__(256) void attn_kernel(
    const float4* __restrict__ nbr_node4, const float4* __restrict__ nbr_time4,
    const float4* __restrict__ nbr_edge4, const int* __restrict__ masks)
{
    const int b = blockIdx.x;
    __shared__ float4 kv4[NNB][112];   // 35 KB
    __shared__ float4 qk4[NH][112];    // 7 KB
    __shared__ float  prob[NH][NNB];
    __shared__ int    msk[NNB];

    const int tid = threadIdx.x;
    const int warp = tid >> 5, lane = tid & 31;

    const float4* np = nbr_node4 + (size_t)b * NNB * 43;
    for (int i = tid; i < NNB * 43; i += 256) cp16(&kv4[i / 43][i % 43], np + i);
    const float4* ep = nbr_edge4 + (size_t)b * NNB * 43;
    for (int i = tid; i < NNB * 43; i += 256) cp16(&kv4[i / 43][43 + i % 43], ep + i);
    const float4* tp = nbr_time4 + (size_t)b * NNB * 25;
    for (int i = tid; i < NNB * 25; i += 256) cp16(&kv4[i / 25][86 + i % 25], tp + i);
    const float4* qp = (const float4*)g_qk + (size_t)b * 448;
    for (int i = tid; i < 448; i += 256) cp16(&((float4*)qk4)[i], qp + i);
    if (tid < 5) cp16(&msk[tid * 4], masks + b * NNB + tid * 4);
    if (tid < NNB) kv4[tid][111] = make_float4(0.f, 0.f, 0.f, 0.f);
    cp_commit();
    cp_wait<0>();
    __syncthreads();

    // 80 score dot-products; 10 per warp
    for (int p = warp * 10; p < warp * 10 + 10; p++) {
        int h = p / NNB, n = p % NNB;
        float acc = 0.0f;
#pragma unroll
        for (int t = 0; t < 4; t++) {
            int c = lane + t * 32;
            if (c < 112) {
                float4 q = qk4[h][c], k = kv4[n][c];
                acc += q.x * k.x + q.y * k.y + q.z * k.z + q.w * k.w;
            }
        }
#pragma unroll
        for (int off = 16; off; off >>= 1) acc += __shfl_xor_sync(0xffffffffu, acc, off);
        if (lane == 0)
            prob[h][n] = (msk[n] == 0) ? -1e10f : acc * SCALE;
    }
    __syncthreads();

    if (warp < NH) {
        float s = (lane < NNB) ? prob[warp][lane] : -3.0e38f;
        float m = s;
#pragma unroll
        for (int off = 16; off; off >>= 1) m = fmaxf(m, __shfl_xor_sync(0xffffffffu, m, off));
        float e = (lane < NNB) ? expf(s - m) : 0.0f;
        float sum = e;
#pragma unroll
        for (int off = 16; off; off >>= 1) sum += __shfl_xor_sync(0xffffffffu, sum, off);
        if (lane < NNB) prob[warp][lane] = e / sum;
    }
    __syncthreads();

    float4* zp = (float4*)g_z + (size_t)b * 448;
    for (int i = tid; i < 448; i += 256) {
        int h = i / 112, c = i % 112;
        float4 a = make_float4(0.f, 0.f, 0.f, 0.f);
#pragma unroll
        for (int n = 0; n < NNB; n++) {
            float w = prob[h][n];
            float4 k = kv4[n][c];
            a.x += w * k.x; a.y += w * k.y; a.z += w * k.z; a.w += w * k.w;
        }
        a.x = rnd_tf32(a.x); a.y = rnd_tf32(a.y);
        a.z = rnd_tf32(a.z); a.w = rnd_tf32(a.w);
        zp[i] = a;
    }
}

// ---------------------------------------------------------------------------
// LN epilogue: x = y + br + residual;  out = (x-mu)*rsqrt(var+eps)*gamma+beta
// ---------------------------------------------------------------------------
__global__ __launch_bounds__(256) void ln_kernel(
    const float4* __restrict__ node4, const float4* __restrict__ time4,
    const float4* __restrict__ br4, const float4* __restrict__ g4,
    const float4* __restrict__ be4, float4* __restrict__ out4)
{
    const int warp = threadIdx.x >> 5, lane = threadIdx.x & 31;
    const int b = blockIdx.x * 8 + warp;
    const float4* y4 = (const float4*)g_y;

    float4 v[3];
    float sum = 0.f, sum2 = 0.f;
#pragma unroll
    for (int t = 0; t < 3; t++) {
        int c = lane + t * 32;
        if (c < 68) {
            float4 x = y4[(size_t)b * 68 + c];
            float4 r = (c < 43) ? node4[(size_t)b * 43 + c]
                                : time4[(size_t)b * 25 + (c - 43)];
            float4 bb = br4[c];
            x.x += r.x + bb.x; x.y += r.y + bb.y;
            x.z += r.z + bb.z; x.w += r.w + bb.w;
            v[t] = x;
            sum  += x.x + x.y + x.z + x.w;
            sum2 += x.x * x.x + x.y * x.y + x.z * x.z + x.w * x.w;
        }
    }
#pragma unroll
    for (int off = 16; off; off >>= 1) {
        sum  += __shfl_xor_sync(0xffffffffu, sum,  off);
        sum2 += __shfl_xor_sync(0xffffffffu, sum2, off);
    }
    const float mu = sum * (1.0f / OUT_DIM);
    const float var = sum2 * (1.0f / OUT_DIM) - mu * mu;
    const float rs = rsqrtf(var + LN_EPS);
#pragma unroll
    for (int t = 0; t < 3; t++) {
        int c = lane + t * 32;
        if (c < 68) {
            float4 gg = g4[c], be = be4[c];
            float4 o;
            o.x = (v[t].x - mu) * rs * gg.x + be.x;
            o.y = (v[t].y - mu) * rs * gg.y + be.y;
            o.z = (v[t].z - mu) * rs * gg.z + be.z;
            o.w = (v[t].w - mu) * rs * gg.w + be.w;
            out4[(size_t)b * 68 + c] = o;
        }
    }
}

// ---------------------------------------------------------------------------
extern "C" void kernel_launch(void* const* d_in, const int* in_sizes, int n_in,
                              void* d_out, int out_size)
{
    const float* node     = (const float*)d_in[0];
    const float* ntime    = (const float*)d_in[1];
    const float* nbr_node = (const float*)d_in[2];
    const float* nbr_time = (const float*)d_in[3];
    const float* nbr_edge = (const float*)d_in[4];
    const int*   masks    = (const int*)d_in[5];
    const float* Wq       = (const float*)d_in[6];
    const float* Wk       = (const float*)d_in[7];
    const float* Wv       = (const float*)d_in[8];
    const float* Wr       = (const float*)d_in[9];
    const float* br       = (const float*)d_in[10];
    const float* gamma    = (const float*)d_in[11];
    const float* beta     = (const float*)d_in[12];
    float* out = (float*)d_out;

    const int SMEMSZ = (3 * 128 * 36 + 3 * 32 * 68) * 4;   // 81408 B

    cudaFuncSetAttribute(gemm_nn<OUT_DIM, OUT_DIM, true >,
                         cudaFuncAttributeMaxDynamicSharedMemorySize, SMEMSZ);
    cudaFuncSetAttribute(gemm_nn<KEY_PAD, DH,      false>,
                         cudaFuncAttributeMaxDynamicSharedMemorySize, SMEMSZ);
    cudaFuncSetAttribute(gemm_nn<80,      KEY_PAD, true >,
                         cudaFuncAttributeMaxDynamicSharedMemorySize, SMEMSZ);
    cudaFuncSetAttribute(gemm_nn<OUT_DIM, CTXP,    false>,
                         cudaFuncAttributeMaxDynamicSharedMemorySize, SMEMSZ);

    float *g_qinp, *g_qp, *g_qkp, *g_zp, *g_ctxp, *g_yp;
    float *g_W1qp, *g_Wkpp, *g_Wvpp, *g_W3p;
    cudaGetSymbolAddress((void**)&g_qinp, g_qin);
    cudaGetSymbolAddress((void**)&g_qp,   g_q);
    cudaGetSymbolAddress((void**)&g_qkp,  g_qk);
    cudaGetSymbolAddress((void**)&g_zp,   g_z);
    cudaGetSymbolAddress((void**)&g_ctxp, g_ctx);
    cudaGetSymbolAddress((void**)&g_yp,   g_y);
    cudaGetSymbolAddress((void**)&g_W1qp, g_W1q);
    cudaGetSymbolAddress((void**)&g_Wkpp, g_Wkp);
    cudaGetSymbolAddress((void**)&g_Wvpp, g_Wvp);
    cudaGetSymbolAddress((void**)&g_W3p,  g_W3);

    // preps
    prep_qin    <<<(BATCH * 68 + 255) / 256, 256>>>((const float4*)node, (const float4*)ntime);
    prep_weights<<<(PW_TOT + 255) / 256, 256>>>(Wq, Wk, Wv, Wr);

    // q = qin @ Wq^T     [B,272]
    gemm_nn<OUT_DIM, OUT_DIM, true>
        <<<dim3(5, BATCH / 128, 1), 256, SMEMSZ>>>(
            g_qinp, OUT_DIM, 0, g_W1qp, OUT_DIM, 0, g_qp, OUT_DIM, 0);

    // qk_h = q_h @ Wk_h  [B,4,448]
    gemm_nn<KEY_PAD, DH, false>
        <<<dim3(7, BATCH / 128, NH), 256, SMEMSZ>>>(
            g_qp, OUT_DIM, DH, g_Wkpp, KEY_PAD, DH * KEY_PAD, g_qkp, BIGN, KEY_PAD);

    // streaming attention -> z [B,1792]
    attn_kernel<<<BATCH, 256>>>((const float4*)nbr_node, (const float4*)nbr_time,
                                (const float4*)nbr_edge, masks);

    // ctx_h = z_h @ Wv_h^T  [B,4,80]
    gemm_nn<80, KEY_PAD, true>
        <<<dim3(2, BATCH / 128, NH), 256, SMEMSZ>>>(
            g_zp, BIGN, KEY_PAD, g_Wvpp, 80, KEY_PAD * 80, g_ctxp, CTXP, 80);

    // y = ctxp @ W3   [B,272]
    gemm_nn<OUT_DIM, CTXP, false>
        <<<dim3(5, BATCH / 128, 1), 256, SMEMSZ>>>(
            g_ctxp, CTXP, 0, g_W3p, OUT_DIM, 0, g_yp, OUT_DIM, 0);

    // LN(y + br + residual)
    ln_kernel<<<BATCH / 8, 256>>>((const float4*)node, (const float4*)ntime,
                                  (const float4*)br, (const float4*)gamma,
                                  (const float4*)beta, (float4*)out);
}